// round 9
// baseline (speedup 1.0000x reference)
#include <cuda_runtime.h>
#include <math.h>

#define BATCH 65536
#define TPB   256

// Global scratch for the per-element solve (harness-sanctioned __device__
// arrays). Layout [element_idx][batch] so warp accesses coalesce.
__device__ double g_S[1024ULL * BATCH];
__device__ double g_M[1024ULL * BATCH];

#define S_AT(i, j) g_S[(size_t)((i) * 32 + (j)) * BATCH + b]
#define M_AT(i, j) g_M[(size_t)((i) * 32 + (j)) * BATCH + b]

// Reference transliteration: one thread per batch element, serial f64 math,
// f64 LU with partial pivoting (physical row swaps). Diagnostic round.
__global__ void kalman_serial_kernel(
    const float* __restrict__ x_post, const float* __restrict__ P_post,
    const float* __restrict__ ctx,    const float* __restrict__ meas,
    const float* __restrict__ W1,     const float* __restrict__ b1,
    const float* __restrict__ W2,     const float* __restrict__ b2,
    const float* __restrict__ Hm,     const float* __restrict__ logQ,
    const float* __restrict__ logR,
    float* __restrict__ out_x, float* __restrict__ out_P)
{
    __shared__ float W1s[64 * 48];
    __shared__ float W2s[32 * 64];
    __shared__ float Hs[32 * 32];
    __shared__ float b1s[64], b2s[32], eQs[32], eRs[32];

    const int tid = threadIdx.x;
    for (int i = tid; i < 64 * 48; i += TPB) W1s[i] = W1[i];
    for (int i = tid; i < 32 * 64; i += TPB) W2s[i] = W2[i];
    for (int i = tid; i < 32 * 32; i += TPB) Hs[i]  = Hm[i];
    if (tid < 64) b1s[tid] = b1[tid];
    if (tid < 32) {
        b2s[tid] = b2[tid];
        eQs[tid] = expf(logQ[tid]);
        eRs[tid] = expf(logR[tid]) + 1e-6f;   // R diag + 1e-6 jitter
    }
    __syncthreads();

    const int b = blockIdx.x * TPB + tid;
    if (b >= BATCH) return;

    // ---------------- MLP: x_pred (f64 accumulation) ----------------
    double in48[48];
    for (int i = 0; i < 32; i++) in48[i] = (double)x_post[(size_t)b * 32 + i];
    for (int i = 0; i < 16; i++) in48[32 + i] = (double)ctx[(size_t)b * 16 + i];

    double h[64];
    for (int o = 0; o < 64; o++) {
        double acc = (double)b1s[o];
        for (int j = 0; j < 48; j++) acc += (double)W1s[o * 48 + j] * in48[j];
        h[o] = tanh(acc);
    }
    double xp[32];
    for (int o = 0; o < 32; o++) {
        double acc = (double)b2s[o];
        for (int k = 0; k < 64; k++) acc += (double)W2s[o * 64 + k] * h[k];
        xp[o] = acc;
    }

    // ---------------- innovation y = meas - x_pred @ H^T ----------------
    double y[32];
    for (int i = 0; i < 32; i++) {
        double acc = (double)meas[(size_t)b * 32 + i];
        for (int j = 0; j < 32; j++) acc -= xp[j] * (double)Hs[i * 32 + j];
        y[i] = acc;
    }

    // ---------------- P_pred (f32, matching reference storage) ----------------
    float Pl[1024];
    {
        const float* Pr = P_post + (size_t)b * 1024;
        for (int i = 0; i < 1024; i++) Pl[i] = Pr[i];
        for (int i = 0; i < 32; i++) Pl[i * 32 + i] += eQs[i];
    }

    // ---------------- M = H @ P_pred (f64). P symmetric => M is also the
    // transposed RHS (P H^T)^T used by linalg.solve. ----------------
    for (int i = 0; i < 32; i++)
        for (int j = 0; j < 32; j++) {
            double acc = 0.0;
            for (int m = 0; m < 32; m++)
                acc += (double)Hs[i * 32 + m] * (double)Pl[m * 32 + j];
            M_AT(i, j) = acc;
        }

    // ---------------- S = M @ H^T + diag(eR + 1e-6) ----------------
    for (int i = 0; i < 32; i++)
        for (int k = 0; k < 32; k++) {
            double acc = 0.0;
            for (int j = 0; j < 32; j++)
                acc += M_AT(i, j) * (double)Hs[k * 32 + j];
            if (k == i) acc += (double)eRs[i];
            S_AT(i, k) = acc;
        }

    // ---------------- LU, partial pivoting, physical swaps, f64 ----------------
    for (int k = 0; k < 32; k++) {
        int p = k;
        double best = fabs(S_AT(k, k));
        for (int i = k + 1; i < 32; i++) {
            double a = fabs(S_AT(i, k));
            if (a > best) { best = a; p = i; }
        }
        if (p != k) {
            for (int j = 0; j < 32; j++) {
                double t = S_AT(k, j); S_AT(k, j) = S_AT(p, j); S_AT(p, j) = t;
                t = M_AT(k, j); M_AT(k, j) = M_AT(p, j); M_AT(p, j) = t;
            }
        }
        double inv = 1.0 / S_AT(k, k);
        for (int i = k + 1; i < 32; i++) {
            double l = S_AT(i, k) * inv;
            for (int j = k + 1; j < 32; j++)
                S_AT(i, j) = fma(-l, S_AT(k, j), S_AT(i, j));
            for (int j = 0; j < 32; j++)
                M_AT(i, j) = fma(-l, M_AT(k, j), M_AT(i, j));
        }
    }
    // back substitution: M becomes X = S^{-1} (P H^T)^T;  K = X^T
    for (int k = 31; k >= 0; k--) {
        double inv = 1.0 / S_AT(k, k);
        for (int j = 0; j < 32; j++) {
            double acc = M_AT(k, j);
            for (int i = k + 1; i < 32; i++)
                acc = fma(-S_AT(k, i), M_AT(i, j), acc);
            M_AT(k, j) = acc * inv;
        }
    }

    // ---------------- x_upd = x_pred + K y   (K[t][j] = X[j][t]) ----------------
    for (int t = 0; t < 32; t++) {
        double acc = xp[t];
        for (int j = 0; j < 32; j++) acc += M_AT(j, t) * y[j];
        out_x[(size_t)b * 32 + t] = (float)acc;
    }

    // ---------------- P_upd = (I - K H) @ P_pred ----------------
    for (int t = 0; t < 32; t++) {
        double ar[32];
        for (int k = 0; k < 32; k++) {
            double acc = 0.0;
            for (int i = 0; i < 32; i++)
                acc += M_AT(i, t) * (double)Hs[i * 32 + k];   // (K H)[t][k]
            ar[k] = ((k == t) ? 1.0 : 0.0) - acc;
        }
        for (int j = 0; j < 32; j++) {
            double acc = 0.0;
            for (int k = 0; k < 32; k++)
                acc += ar[k] * (double)Pl[k * 32 + j];
            out_P[(size_t)b * 1024 + t * 32 + j] = (float)acc;
        }
    }
}

extern "C" void kernel_launch(void* const* d_in, const int* in_sizes, int n_in,
                              void* d_out, int out_size) {
    const float* x_post = (const float*)d_in[0];
    const float* P_post = (const float*)d_in[1];
    const float* ctx    = (const float*)d_in[2];
    const float* meas   = (const float*)d_in[3];
    const float* W1     = (const float*)d_in[4];
    const float* b1     = (const float*)d_in[5];
    const float* W2     = (const float*)d_in[6];
    const float* b2     = (const float*)d_in[7];
    const float* Hm     = (const float*)d_in[8];
    const float* logQ   = (const float*)d_in[9];
    const float* logR   = (const float*)d_in[10];

    float* out_x = (float*)d_out;
    float* out_P = out_x + (size_t)BATCH * 32;

    kalman_serial_kernel<<<BATCH / TPB, TPB>>>(x_post, P_post, ctx, meas,
                                               W1, b1, W2, b2, Hm, logQ, logR,
                                               out_x, out_P);
}

// round 10
// speedup vs baseline: 4.9006x; 4.9006x over previous
#include <cuda_runtime.h>
#include <math.h>

#define BATCH 65536
#define WPB   4
#define TPB   128
#define H_ST  36
#define P_ST  36
#define X_ST  33
#define W1_ST 49
#define W2_ST 65
#define FULL  0xffffffffu

// ---------- double-float (compensated f32) primitives ----------
// acc (sh,sl) += a*b, a,b f32. Dot2: TwoProdFMA + exact TwoSum.
__device__ __forceinline__ void acc2(float a, float b, float& sh, float& sl) {
    float p = a * b;
    float e = fmaf(a, b, -p);
    float t = sh + p;
    float z = t - sh;
    sl += ((sh - (t - z)) + (p - z)) + e;
    sh = t;
}
// acc (sh,sl) += (ah,al)*b, b f32.
__device__ __forceinline__ void acc2df(float ah, float al, float b, float& sh, float& sl) {
    float p = ah * b;
    float e = fmaf(ah, b, -p);
    e = fmaf(al, b, e);
    float t = sh + p;
    float z = t - sh;
    sl += ((sh - (t - z)) + (p - z)) + e;
    sh = t;
}
// (rh,rl) -= (ah,al)*(bh,bl)
__device__ __forceinline__ void sub2(float ah, float al, float bh, float bl,
                                     float& rh, float& rl) {
    float p = ah * bh;
    float e = fmaf(ah, bh, -p);
    e = fmaf(ah, bl, e);
    e = fmaf(al, bh, e);
    float t = rh - p;
    float z = t - rh;
    rl += ((rh - (t - z)) - (p + z)) - e;
    rh = t;
}
// (ph,pl) = (ah,al)*(bh,bl)
__device__ __forceinline__ void dmul(float ah, float al, float bh, float bl,
                                     float& ph, float& pl) {
    ph = ah * bh;
    pl = fmaf(ah, bh, -ph);
    pl = fmaf(ah, bl, pl);
    pl = fmaf(al, bh, pl);
}
// (qh,ql) = 1/(dh,dl)
__device__ __forceinline__ void drecip(float dh, float dl, float& qh, float& ql) {
    float q = 1.0f / dh;
    float e = fmaf(-q, dh, 1.0f);
    e = fmaf(-q, dl, e);
    float q1 = q * e;
    float t = q + q1;          // Fast2Sum valid: |q| >= |q1|
    ql = (q - t) + q1;
    qh = t;
}

__global__ void __launch_bounds__(TPB, 2) kalman_kernel(
    const float* __restrict__ x_post, const float* __restrict__ P_post,
    const float* __restrict__ ctx,    const float* __restrict__ meas,
    const float* __restrict__ W1,     const float* __restrict__ b1,
    const float* __restrict__ W2,     const float* __restrict__ b2,
    const float* __restrict__ Hm,     const float* __restrict__ logQ,
    const float* __restrict__ logR,
    float* __restrict__ out_x, float* __restrict__ out_P)
{
    __shared__ __align__(16) float Hs[32 * H_ST];
    __shared__ __align__(16) union SU {
        struct { float W1s[64 * W1_ST]; float W2s[32 * W2_ST]; } m;  // MLP phase
        float xt[WPB][32 * X_ST];                                    // X = S^-1 M
    } u;
    __shared__ __align__(16) float Pt[WPB][32 * P_ST];   // P_pred rows (f32)
    __shared__ float b1s[64], b2s[32], eQs[32], eRs[32];
    __shared__ float mlpbuf[WPB][64];
    __shared__ float ybuf[WPB][32];

    const int tid = threadIdx.x;
    for (int i = tid; i < 64 * 48; i += TPB) u.m.W1s[(i / 48) * W1_ST + (i % 48)] = W1[i];
    for (int i = tid; i < 32 * 64; i += TPB) u.m.W2s[(i >> 6) * W2_ST + (i & 63)] = W2[i];
    for (int i = tid; i < 32 * 32; i += TPB) Hs[(i >> 5) * H_ST + (i & 31)] = Hm[i];
    if (tid < 64) b1s[tid] = b1[tid];
    if (tid < 32) {
        b2s[tid] = b2[tid];
        eQs[tid] = expf(logQ[tid]);
        eRs[tid] = expf(logR[tid]) + 1e-6f;
    }
    __syncthreads();

    const int w    = tid >> 5;
    const int lane = tid & 31;
    const int b    = blockIdx.x * WPB + w;
    float* tP = Pt[w];

    float hrow[32];
#pragma unroll
    for (int j = 0; j < 32; j++) hrow[j] = Hs[lane * H_ST + j];

    // ===================== MLP (f32, noise-benign) =====================
    mlpbuf[w][lane] = x_post[(size_t)b * 32 + lane];
    if (lane < 16) mlpbuf[w][32 + lane] = ctx[(size_t)b * 16 + lane];
    __syncwarp();

    float a0 = b1s[lane], a1 = b1s[lane + 32];
#pragma unroll
    for (int j = 0; j < 48; j++) {
        float vj = mlpbuf[w][j];
        a0 = fmaf(u.m.W1s[lane * W1_ST + j], vj, a0);
        a1 = fmaf(u.m.W1s[(lane + 32) * W1_ST + j], vj, a1);
    }
    float h0 = tanhf(a0), h1 = tanhf(a1);
    __syncwarp();
    mlpbuf[w][lane]      = h0;
    mlpbuf[w][lane + 32] = h1;
    __syncwarp();

    float xp = b2s[lane];
#pragma unroll
    for (int k = 0; k < 64; k++) xp = fmaf(u.m.W2s[lane * W2_ST + k], mlpbuf[w][k], xp);
    __syncwarp();
    mlpbuf[w][lane] = xp;
    __syncwarp();

    float yv = meas[(size_t)b * 32 + lane];
#pragma unroll
    for (int j = 0; j < 32; j++) yv = fmaf(-mlpbuf[w][j], hrow[j], yv);
    ybuf[w][lane] = yv;

    // All warps must finish W1/W2 reads before anyone writes the X overlay.
    __syncthreads();

    // ===== P_pred rows into shared (f32, matches reference storage) =====
    {
        const float4* Pr = (const float4*)(P_post + (size_t)b * 1024 + lane * 32);
        float4* tr = (float4*)(tP + lane * P_ST);
#pragma unroll
        for (int j4 = 0; j4 < 8; j4++) tr[j4] = Pr[j4];
    }
    __syncwarp();
    tP[lane * P_ST + lane] += eQs[lane];
    __syncwarp();

    // ===== M row `lane` = H[lane][:] @ P  (df, Dot2). Doubles as RHS B. =====
    float bh[32], bl[32];
#pragma unroll
    for (int j = 0; j < 32; j++) { bh[j] = 0.f; bl[j] = 0.f; }
#pragma unroll
    for (int k = 0; k < 32; k++) {
        float hk = hrow[k];
        const float4* pr = (const float4*)(tP + k * P_ST);
#pragma unroll
        for (int j4 = 0; j4 < 8; j4++) {
            float4 p4 = pr[j4];
            acc2(hk, p4.x, bh[4 * j4 + 0], bl[4 * j4 + 0]);
            acc2(hk, p4.y, bh[4 * j4 + 1], bl[4 * j4 + 1]);
            acc2(hk, p4.z, bh[4 * j4 + 2], bl[4 * j4 + 2]);
            acc2(hk, p4.w, bh[4 * j4 + 3], bl[4 * j4 + 3]);
        }
    }

    // ===== S row `lane` = M_df[lane][:] @ H^T + diag(eR)  (df) =====
    float sh[32], sl[32];
#pragma unroll
    for (int k = 0; k < 32; k++) {
        const float4* hr = (const float4*)(Hs + k * H_ST);
        float ach = 0.f, acl = 0.f;
#pragma unroll
        for (int j4 = 0; j4 < 8; j4++) {
            float4 h4 = hr[j4];
            acc2df(bh[4 * j4 + 0], bl[4 * j4 + 0], h4.x, ach, acl);
            acc2df(bh[4 * j4 + 1], bl[4 * j4 + 1], h4.y, ach, acl);
            acc2df(bh[4 * j4 + 2], bl[4 * j4 + 2], h4.z, ach, acl);
            acc2df(bh[4 * j4 + 3], bl[4 * j4 + 3], h4.w, ach, acl);
        }
        if (k == lane) {   // += eR (exact TwoSum)
            float eR = eRs[lane];
            float t = ach + eR;
            float z = t - ach;
            acl += (ach - (t - z)) + (eR - z);
            ach = t;
        }
        sh[k] = ach; sl[k] = acl;
    }

    // ===== df LU with partial pivoting (virtual swaps), RHS through =====
    int   myk   = 32;
    int   mypiv = 0;
    float myih = 0.f, myil = 0.f;
    bool  done = false;

#pragma unroll
    for (int k = 0; k < 32; k++) {
        float cand = done ? -1.0f : fabsf(sh[k]);
        int   idx  = lane;
#pragma unroll
        for (int off = 16; off > 0; off >>= 1) {
            float oc = __shfl_xor_sync(FULL, cand, off);
            int   oi = __shfl_xor_sync(FULL, idx,  off);
            if (oc > cand || (oc == cand && oi < idx)) { cand = oc; idx = oi; }
        }
        if (lane == k) mypiv = idx;
        float dh_ = __shfl_sync(FULL, sh[k], idx);
        float dl_ = __shfl_sync(FULL, sl[k], idx);
        float ih, il; drecip(dh_, dl_, ih, il);
        if (lane == idx) { myk = k; myih = ih; myil = il; done = true; }
        float lh, ll;
        dmul(sh[k], sl[k], ih, il, lh, ll);
        if (done) { lh = 0.f; ll = 0.f; }
#pragma unroll
        for (int j = k + 1; j < 32; j++) {
            float uh = __shfl_sync(FULL, sh[j], idx);
            float ul = __shfl_sync(FULL, sl[j], idx);
            sub2(lh, ll, uh, ul, sh[j], sl[j]);
        }
#pragma unroll
        for (int j = 0; j < 32; j++) {
            float uh = __shfl_sync(FULL, bh[j], idx);
            float ul = __shfl_sync(FULL, bl[j], idx);
            sub2(lh, ll, uh, ul, bh[j], bl[j]);
        }
    }

    // ===== df backward substitution (reverse pivot order) =====
#pragma unroll
    for (int k = 31; k >= 0; k--) {
        int pk = __shfl_sync(FULL, mypiv, k);
        if (myk == k) {
#pragma unroll
            for (int j = 0; j < 32; j++) {
                float th, tl;
                dmul(bh[j], bl[j], myih, myil, th, tl);
                bh[j] = th; bl[j] = tl;
            }
        }
#pragma unroll
        for (int j = 0; j < 32; j++) {
            float xh = __shfl_sync(FULL, bh[j], pk);
            float xl = __shfl_sync(FULL, bl[j], pk);
            if (myk < k) sub2(sh[k], sl[k], xh, xl, bh[j], bl[j]);
        }
    }

    // X row `myk` -> shared (single f32 rounding, benign)
    {
        float* xr = u.xt[w] + myk * X_ST;
#pragma unroll
        for (int j = 0; j < 32; j++) xr[j] = bh[j] + bl[j];
    }
    __syncwarp();

    // ===== downstream (f32): K = X^T =====
    float xcol[32];
#pragma unroll
    for (int i = 0; i < 32; i++) xcol[i] = u.xt[w][i * X_ST + lane];

    float xo = xp;
#pragma unroll
    for (int j = 0; j < 32; j++) xo = fmaf(xcol[j], ybuf[w][j], xo);
    out_x[(size_t)b * 32 + lane] = xo;

    // A row t = I - K H
    float g2[32];
#pragma unroll
    for (int j = 0; j < 32; j++) g2[j] = 0.f;
#pragma unroll
    for (int i = 0; i < 32; i++) {
        float kv = xcol[i];
        const float4* hr = (const float4*)(Hs + i * H_ST);
#pragma unroll
        for (int j4 = 0; j4 < 8; j4++) {
            float4 h4 = hr[j4];
            g2[4 * j4 + 0] = fmaf(kv, h4.x, g2[4 * j4 + 0]);
            g2[4 * j4 + 1] = fmaf(kv, h4.y, g2[4 * j4 + 1]);
            g2[4 * j4 + 2] = fmaf(kv, h4.z, g2[4 * j4 + 2]);
            g2[4 * j4 + 3] = fmaf(kv, h4.w, g2[4 * j4 + 3]);
        }
    }
#pragma unroll
    for (int j = 0; j < 32; j++)
        g2[j] = ((j == lane) ? 1.0f : 0.0f) - g2[j];

    // P_upd row t = A[t][:] @ P_pred
    float pu[32];
#pragma unroll
    for (int j = 0; j < 32; j++) pu[j] = 0.f;
#pragma unroll
    for (int k = 0; k < 32; k++) {
        float ak = g2[k];
        const float4* pr = (const float4*)(tP + k * P_ST);
#pragma unroll
        for (int j4 = 0; j4 < 8; j4++) {
            float4 p4 = pr[j4];
            pu[4 * j4 + 0] = fmaf(ak, p4.x, pu[4 * j4 + 0]);
            pu[4 * j4 + 1] = fmaf(ak, p4.y, pu[4 * j4 + 1]);
            pu[4 * j4 + 2] = fmaf(ak, p4.z, pu[4 * j4 + 2]);
            pu[4 * j4 + 3] = fmaf(ak, p4.w, pu[4 * j4 + 3]);
        }
    }
    float4* Po = (float4*)(out_P + (size_t)b * 1024 + lane * 32);
#pragma unroll
    for (int j4 = 0; j4 < 8; j4++)
        Po[j4] = make_float4(pu[4 * j4], pu[4 * j4 + 1], pu[4 * j4 + 2], pu[4 * j4 + 3]);
}

extern "C" void kernel_launch(void* const* d_in, const int* in_sizes, int n_in,
                              void* d_out, int out_size) {
    const float* x_post = (const float*)d_in[0];
    const float* P_post = (const float*)d_in[1];
    const float* ctx    = (const float*)d_in[2];
    const float* meas   = (const float*)d_in[3];
    const float* W1     = (const float*)d_in[4];
    const float* b1     = (const float*)d_in[5];
    const float* W2     = (const float*)d_in[6];
    const float* b2     = (const float*)d_in[7];
    const float* Hm     = (const float*)d_in[8];
    const float* logQ   = (const float*)d_in[9];
    const float* logR   = (const float*)d_in[10];

    float* out_x = (float*)d_out;
    float* out_P = out_x + (size_t)BATCH * 32;

    kalman_kernel<<<BATCH / WPB, TPB>>>(x_post, P_post, ctx, meas,
                                        W1, b1, W2, b2, Hm, logQ, logR,
                                        out_x, out_P);
}